// round 7
// baseline (speedup 1.0000x reference)
#include <cuda_runtime.h>
#include <cuda_bf16.h>
#include <cstdint>

// ModalConditionedRPE, GB300 sm_103a. Two kernels.
// R7 = R5 main loop + explicit 2-deep software pipeline (double-buffered
// a/b/w2 LDS prefetch one hp ahead) and no register cap: trades occupancy
// (4->3 blocks/SM) for intra-warp ILP to close the 66.6% issue gap.
// (R6's packed max.f32x2 does not exist on sm_103a; relu stays scalar FMNMX.)
//
// out[i,j] = b2 + sum_h relu(P[i,h] + Q[j,h]) * W2[h]
//   P[i,h] = x_i*W1[0,h] + y_i*W1[1,h] + s_mean[i]*W1[34,h] + Cmod[h]
//   Q[j,h] = -x_j*W1[0,h] - y_j*W1[1,h] + s_mean[j]*W1[35,h]
// s_mean: jax.image.resize 80->40 linear antialias (4-tap triangle,
// edge-renormalized), mean over batch of 4. (Validated rel_err 7.4e-8.)

#define NPIX 1600
#define HDIM 64
#define PAD  66   // smem row stride in floats (conflict-free for tx stride)

typedef unsigned long long u64;
union F2u { u64 u; float2 f; };

__device__ __forceinline__ u64 add2(u64 a, u64 b) {
    u64 r; asm("add.rn.f32x2 %0, %1, %2;" : "=l"(r) : "l"(a), "l"(b)); return r;
}
__device__ __forceinline__ u64 fma2(u64 a, u64 b, u64 c) {
    u64 r; asm("fma.rn.f32x2 %0, %1, %2, %3;" : "=l"(r) : "l"(a), "l"(b), "l"(c)); return r;
}
__device__ __forceinline__ void stg_cs(float* p, float v) {
    asm volatile("st.global.cs.f32 [%0], %1;" :: "l"(p), "f"(v) : "memory");
}

__device__ float g_P[NPIX * HDIM];
__device__ float g_Q[NPIX * HDIM];

// 4-tap antialiased triangle weights for the 80->40 downsample.
__device__ __forceinline__ void resize_taps(int o, float* w, int& t0) {
    t0 = 2 * o - 1;
    float ww[4] = { 0.25f, 0.75f, 0.75f, 0.25f };
    float s = 0.f;
#pragma unroll
    for (int k = 0; k < 4; k++) {
        int ii = t0 + k;
        if (ii < 0 || ii >= 80) ww[k] = 0.f;
        s += ww[k];
    }
    float inv = 1.f / s;
#pragma unroll
    for (int k = 0; k < 4; k++) w[k] = ww[k] * inv;
}

// Kernel 1: grid 25 x 256. Block covers pixels [64*bid, +64).
__global__ __launch_bounds__(256) void precompute_kernel(
    const float* __restrict__ smap,   // (4,1,80,80)
    const float* __restrict__ me,     // (3,16)
    const float* __restrict__ W1,     // (36,64)
    const float* __restrict__ b1,     // (64)
    const int*   __restrict__ qmod,
    const int*   __restrict__ kmod)
{
    __shared__ float sm[64];
    __shared__ float cm[HDIM];
    const int t  = threadIdx.x;
    const int i0 = blockIdx.x * 64;

    // Phase A: s_mean; t -> (pixel t>>2, batch t&3), shfl-reduce over batch.
    {
        int li = t >> 2, b = t & 3;
        int i  = i0 + li;
        int iy = i / 40, ix = i % 40;
        float wy[4], wx[4]; int ty0, tx0;
        resize_taps(iy, wy, ty0);
        resize_taps(ix, wx, tx0);
        const float* base = smap + b * 6400;
        float s = 0.f;
#pragma unroll
        for (int a = 0; a < 4; a++) {
            if (wy[a] == 0.f) continue;
            int yy = ty0 + a;
            float rowacc = 0.f;
#pragma unroll
            for (int c = 0; c < 4; c++) {
                if (wx[c] == 0.f) continue;
                rowacc += wx[c] * base[yy * 80 + tx0 + c];
            }
            s += wy[a] * rowacc;
        }
        s += __shfl_xor_sync(0xffffffffu, s, 1);
        s += __shfl_xor_sync(0xffffffffu, s, 2);
        if (b == 0) sm[li] = s * 0.25f;
    }
    // Phase B: Cmod
    if (t >= 128 && t < 192) {
        int h = t - 128;
        int q = qmod[0], km = kmod[0];
        float c = b1[h];
#pragma unroll
        for (int kk = 0; kk < 16; kk++) {
            c += me[q  * 16 + kk] * W1[(2  + kk) * HDIM + h];
            c += me[km * 16 + kk] * W1[(18 + kk) * HDIM + h];
        }
        cm[h] = c;
    }
    __syncthreads();

    // Phase C: P/Q rows (coalesced over h).
    for (int p = t; p < 64 * HDIM; p += 256) {
        int r = p >> 6, h = p & 63;
        int i  = i0 + r;
        float x = -0.5f + (float)(i % 40) * (1.0f / 39.0f);
        float y = -0.5f + (float)(i / 40) * (1.0f / 39.0f);
        float w0  = W1[h];
        float w1  = W1[HDIM + h];
        float sv  = sm[r];
        g_P[i * HDIM + h] =  x * w0 + y * w1 + sv * W1[34 * HDIM + h] + cm[h];
        g_Q[i * HDIM + h] = -x * w0 - y * w1 + sv * W1[35 * HDIM + h];
    }
}

// Kernel 2: 64x64 tile / block, 4x4 per thread, packed f32x2 math with a
// 2-deep software pipeline on the LDS operand loads.
__global__ __launch_bounds__(256) void rpe_main_kernel(
    const float* __restrict__ W2,   // (64)
    const float* __restrict__ b2,   // (1)
    float*       __restrict__ out)  // (1600,1600)
{
    __shared__ __align__(16) float Ps[64 * PAD];
    __shared__ __align__(16) float Qs[64 * PAD];
    __shared__ __align__(16) float w2s[HDIM];

    const int t  = threadIdx.x;
    const int bi = blockIdx.y * 64;
    const int bj = blockIdx.x * 64;

    // Tile fill: 64 rows x 32 float2 per tile; 8 float2 each thread.
#pragma unroll
    for (int k = t; k < 64 * 32; k += 256) {
        int r = k >> 5, c = k & 31;
        float2 vp = *(const float2*)&g_P[(bi + r) * HDIM + 2 * c];
        float2 vq = *(const float2*)&g_Q[(bj + r) * HDIM + 2 * c];
        *(float2*)&Ps[r * PAD + 2 * c] = vp;
        *(float2*)&Qs[r * PAD + 2 * c] = vq;
    }
    if (t < HDIM) w2s[t] = W2[t];
    __syncthreads();

    const int tx = t & 15;   // j group (stride 16)
    const int ty = t >> 4;   // i group (stride 16)

    const float* psB = &Ps[ty * PAD];
    const float* qsB = &Qs[tx * PAD];

    u64 acc[4][4];
#pragma unroll
    for (int r = 0; r < 4; r++)
#pragma unroll
        for (int c = 0; c < 4; c++) acc[r][c] = 0ull;

    u64 a[2][4], b[2][4], w2p[2];

    // Prologue: load hp=0 into buffer 0.
#pragma unroll
    for (int r = 0; r < 4; r++) a[0][r] = *(const u64*)&psB[(16 * r) * PAD];
#pragma unroll
    for (int c = 0; c < 4; c++) b[0][c] = *(const u64*)&qsB[(16 * c) * PAD];
    w2p[0] = *(const u64*)&w2s[0];

#pragma unroll 4
    for (int hp = 0; hp < 32; hp++) {
        const int cur = hp & 1, nxt = cur ^ 1;
        const int hn  = (hp + 1) & 31;   // wraps; last prefetch harmless

        // Prefetch hp+1 operands (off the critical path of this iteration).
#pragma unroll
        for (int r = 0; r < 4; r++)
            a[nxt][r] = *(const u64*)&psB[(16 * r) * PAD + 2 * hn];
#pragma unroll
        for (int c = 0; c < 4; c++)
            b[nxt][c] = *(const u64*)&qsB[(16 * c) * PAD + 2 * hn];
        w2p[nxt] = *(const u64*)&w2s[2 * hn];

        // Compute on current buffer.
#pragma unroll
        for (int r = 0; r < 4; r++) {
#pragma unroll
            for (int c = 0; c < 4; c++) {
                F2u u;
                u.u = add2(a[cur][r], b[cur][c]);   // FADD2
                u.f.x = fmaxf(u.f.x, 0.0f);         // FMNMX
                u.f.y = fmaxf(u.f.y, 0.0f);
                acc[r][c] = fma2(u.u, w2p[cur], acc[r][c]);  // FFMA2
            }
        }
    }

    const float bb = b2[0];
#pragma unroll
    for (int r = 0; r < 4; r++) {
        int gi = bi + ty + 16 * r;
#pragma unroll
        for (int c = 0; c < 4; c++) {
            int gj = bj + tx + 16 * c;
            F2u v; v.u = acc[r][c];
            stg_cs(&out[gi * NPIX + gj], v.f.x + v.f.y + bb);
        }
    }
}

// metadata order: h, w, q_mod, k_mod, structure_map, mod_embed, W1, b1, W2, b2
extern "C" void kernel_launch(void* const* d_in, const int* in_sizes, int n_in,
                              void* d_out, int out_size)
{
    const int*   qmod = (const int*)d_in[2];
    const int*   kmod = (const int*)d_in[3];
    const float* smap = (const float*)d_in[4];
    const float* me   = (const float*)d_in[5];
    const float* W1   = (const float*)d_in[6];
    const float* b1   = (const float*)d_in[7];
    const float* W2   = (const float*)d_in[8];
    const float* b2   = (const float*)d_in[9];
    float* out = (float*)d_out;

    precompute_kernel<<<25, 256>>>(smap, me, W1, b1, qmod, kmod);
    rpe_main_kernel<<<dim3(25, 25), 256>>>(W2, b2, out);
}

// round 8
// speedup vs baseline: 1.2437x; 1.2437x over previous
#include <cuda_runtime.h>
#include <cuda_bf16.h>
#include <cstdint>

// ModalConditionedRPE, GB300 sm_103a. Two kernels.
// R8 = R5 main loop with LDS.128 operand fetches: 9 LDS.128 per 2-hp
// iteration instead of 18 LDS.64, attacking the per-SMSP LDS issue floor
// (eff ~4cy at nw>=4) identified as the 70.7%-issue cap. PAD 66 -> 68 for
// 16B alignment (2-way bank conflict = bandwidth floor, optimal).
//
// out[i,j] = b2 + sum_h relu(P[i,h] + Q[j,h]) * W2[h]
//   P[i,h] = x_i*W1[0,h] + y_i*W1[1,h] + s_mean[i]*W1[34,h] + Cmod[h]
//   Q[j,h] = -x_j*W1[0,h] - y_j*W1[1,h] + s_mean[j]*W1[35,h]
// s_mean: jax.image.resize 80->40 linear antialias (4-tap triangle,
// edge-renormalized), mean over batch of 4. (Validated rel_err 7.4e-8.)

#define NPIX 1600
#define HDIM 64
#define PAD  68   // smem row stride in floats: 16B-aligned rows for LDS.128

typedef unsigned long long u64;
union F2u { u64 u; float2 f; };
union F4u { float4 v; u64 d[2]; };

__device__ __forceinline__ u64 add2(u64 a, u64 b) {
    u64 r; asm("add.rn.f32x2 %0, %1, %2;" : "=l"(r) : "l"(a), "l"(b)); return r;
}
__device__ __forceinline__ u64 fma2(u64 a, u64 b, u64 c) {
    u64 r; asm("fma.rn.f32x2 %0, %1, %2, %3;" : "=l"(r) : "l"(a), "l"(b), "l"(c)); return r;
}
__device__ __forceinline__ void stg_cs(float* p, float v) {
    asm volatile("st.global.cs.f32 [%0], %1;" :: "l"(p), "f"(v) : "memory");
}

__device__ float g_P[NPIX * HDIM];
__device__ float g_Q[NPIX * HDIM];

// 4-tap antialiased triangle weights for the 80->40 downsample.
__device__ __forceinline__ void resize_taps(int o, float* w, int& t0) {
    t0 = 2 * o - 1;
    float ww[4] = { 0.25f, 0.75f, 0.75f, 0.25f };
    float s = 0.f;
#pragma unroll
    for (int k = 0; k < 4; k++) {
        int ii = t0 + k;
        if (ii < 0 || ii >= 80) ww[k] = 0.f;
        s += ww[k];
    }
    float inv = 1.f / s;
#pragma unroll
    for (int k = 0; k < 4; k++) w[k] = ww[k] * inv;
}

// Kernel 1: grid 25 x 256. Block covers pixels [64*bid, +64).
__global__ __launch_bounds__(256) void precompute_kernel(
    const float* __restrict__ smap,   // (4,1,80,80)
    const float* __restrict__ me,     // (3,16)
    const float* __restrict__ W1,     // (36,64)
    const float* __restrict__ b1,     // (64)
    const int*   __restrict__ qmod,
    const int*   __restrict__ kmod)
{
    __shared__ float sm[64];
    __shared__ float cm[HDIM];
    const int t  = threadIdx.x;
    const int i0 = blockIdx.x * 64;

    // Phase A: s_mean; t -> (pixel t>>2, batch t&3), shfl-reduce over batch.
    {
        int li = t >> 2, b = t & 3;
        int i  = i0 + li;
        int iy = i / 40, ix = i % 40;
        float wy[4], wx[4]; int ty0, tx0;
        resize_taps(iy, wy, ty0);
        resize_taps(ix, wx, tx0);
        const float* base = smap + b * 6400;
        float s = 0.f;
#pragma unroll
        for (int a = 0; a < 4; a++) {
            if (wy[a] == 0.f) continue;
            int yy = ty0 + a;
            float rowacc = 0.f;
#pragma unroll
            for (int c = 0; c < 4; c++) {
                if (wx[c] == 0.f) continue;
                rowacc += wx[c] * base[yy * 80 + tx0 + c];
            }
            s += wy[a] * rowacc;
        }
        s += __shfl_xor_sync(0xffffffffu, s, 1);
        s += __shfl_xor_sync(0xffffffffu, s, 2);
        if (b == 0) sm[li] = s * 0.25f;
    }
    // Phase B: Cmod
    if (t >= 128 && t < 192) {
        int h = t - 128;
        int q = qmod[0], km = kmod[0];
        float c = b1[h];
#pragma unroll
        for (int kk = 0; kk < 16; kk++) {
            c += me[q  * 16 + kk] * W1[(2  + kk) * HDIM + h];
            c += me[km * 16 + kk] * W1[(18 + kk) * HDIM + h];
        }
        cm[h] = c;
    }
    __syncthreads();

    // Phase C: P/Q rows (coalesced over h).
    for (int p = t; p < 64 * HDIM; p += 256) {
        int r = p >> 6, h = p & 63;
        int i  = i0 + r;
        float x = -0.5f + (float)(i % 40) * (1.0f / 39.0f);
        float y = -0.5f + (float)(i / 40) * (1.0f / 39.0f);
        float w0  = W1[h];
        float w1  = W1[HDIM + h];
        float sv  = sm[r];
        g_P[i * HDIM + h] =  x * w0 + y * w1 + sv * W1[34 * HDIM + h] + cm[h];
        g_Q[i * HDIM + h] = -x * w0 - y * w1 + sv * W1[35 * HDIM + h];
    }
}

// Kernel 2: 64x64 tile / block, 4x4 per thread, packed f32x2 math,
// LDS.128 operand loads covering 2 hp per fetch.
__global__ __launch_bounds__(256) void rpe_main_kernel(
    const float* __restrict__ W2,   // (64)
    const float* __restrict__ b2,   // (1)
    float*       __restrict__ out)  // (1600,1600)
{
    __shared__ __align__(16) float Ps[64 * PAD];
    __shared__ __align__(16) float Qs[64 * PAD];
    __shared__ __align__(16) float w2s[HDIM];

    const int t  = threadIdx.x;
    const int bi = blockIdx.y * 64;
    const int bj = blockIdx.x * 64;

    // Tile fill with float4: 64 rows x 16 float4 per tile; 4 each thread.
#pragma unroll
    for (int k = t; k < 64 * 16; k += 256) {
        int r = k >> 4, c = k & 15;
        float4 vp = *(const float4*)&g_P[(bi + r) * HDIM + 4 * c];
        float4 vq = *(const float4*)&g_Q[(bj + r) * HDIM + 4 * c];
        *(float4*)&Ps[r * PAD + 4 * c] = vp;
        *(float4*)&Qs[r * PAD + 4 * c] = vq;
    }
    if (t < HDIM) w2s[t] = W2[t];
    __syncthreads();

    const int tx = t & 15;   // j group (stride 16)
    const int ty = t >> 4;   // i group (stride 16)

    const float* psB = &Ps[ty * PAD];
    const float* qsB = &Qs[tx * PAD];

    u64 acc[4][4];
#pragma unroll
    for (int r = 0; r < 4; r++)
#pragma unroll
        for (int c = 0; c < 4; c++) acc[r][c] = 0ull;

#pragma unroll 4
    for (int hp2 = 0; hp2 < 16; hp2++) {
        F4u w24; w24.v = *(const float4*)&w2s[4 * hp2];
        F4u a4[4], b4[4];
#pragma unroll
        for (int r = 0; r < 4; r++)
            a4[r].v = *(const float4*)&psB[(16 * r) * PAD + 4 * hp2];
#pragma unroll
        for (int c = 0; c < 4; c++)
            b4[c].v = *(const float4*)&qsB[(16 * c) * PAD + 4 * hp2];

#pragma unroll
        for (int r = 0; r < 4; r++) {
#pragma unroll
            for (int c = 0; c < 4; c++) {
                F2u u0, u1;
                u0.u = add2(a4[r].d[0], b4[c].d[0]);     // FADD2
                u0.f.x = fmaxf(u0.f.x, 0.0f);            // FMNMX
                u0.f.y = fmaxf(u0.f.y, 0.0f);
                acc[r][c] = fma2(u0.u, w24.d[0], acc[r][c]);  // FFMA2
                u1.u = add2(a4[r].d[1], b4[c].d[1]);
                u1.f.x = fmaxf(u1.f.x, 0.0f);
                u1.f.y = fmaxf(u1.f.y, 0.0f);
                acc[r][c] = fma2(u1.u, w24.d[1], acc[r][c]);
            }
        }
    }

    const float bb = b2[0];
#pragma unroll
    for (int r = 0; r < 4; r++) {
        int gi = bi + ty + 16 * r;
#pragma unroll
        for (int c = 0; c < 4; c++) {
            int gj = bj + tx + 16 * c;
            F2u v; v.u = acc[r][c];
            stg_cs(&out[gi * NPIX + gj], v.f.x + v.f.y + bb);
        }
    }
}

// metadata order: h, w, q_mod, k_mod, structure_map, mod_embed, W1, b1, W2, b2
extern "C" void kernel_launch(void* const* d_in, const int* in_sizes, int n_in,
                              void* d_out, int out_size)
{
    const int*   qmod = (const int*)d_in[2];
    const int*   kmod = (const int*)d_in[3];
    const float* smap = (const float*)d_in[4];
    const float* me   = (const float*)d_in[5];
    const float* W1   = (const float*)d_in[6];
    const float* b1   = (const float*)d_in[7];
    const float* W2   = (const float*)d_in[8];
    const float* b2   = (const float*)d_in[9];
    float* out = (float*)d_out;

    precompute_kernel<<<25, 256>>>(smap, me, W1, b1, qmod, kmod);
    rpe_main_kernel<<<dim3(25, 25), 256>>>(W2, b2, out);
}